// round 14
// baseline (speedup 1.0000x reference)
#include <cuda_runtime.h>
#include <cuda_bf16.h>
#include <math.h>

#define Ldim 4096
#define Edim 512
#define Sdim 1024
#define Hdim 150
#define HP   160
#define MAXN 10
#define Ttot 40915
#define TP   40960

// ---------------------------------------------------------------------------
// Device scratch (zero-init; pad regions never written -> stay zero)
// ---------------------------------------------------------------------------
__device__ float g_A[Ldim * HP];
__device__ float g_B[Ldim * HP];
__device__ float g_C[Ldim * HP];
__device__ float g_attn[Ldim];
__device__ float g_X[(size_t)TP * HP];   // pooled rows, fp32 (pad cols stay 0)
__device__ float g_sW3p[HP];
__device__ float g_sb2p[HP];
__device__ float g_aW3p[HP];
__device__ float g_ab2p[HP];

// bf16 hi/lo triplet buffers.  A-side slot pattern: [xh, xl, xh]
//                              B-side slot pattern: [bh, bh, bl]
__device__ __align__(16) __nv_bfloat16 g_H1s[(size_t)Ldim * 480];
__device__ __align__(16) __nv_bfloat16 g_W1s[3 * 160 * 3072];
__device__ __align__(16) __nv_bfloat16 g_WCs[160 * 1536];
__device__ __align__(16) __nv_bfloat16 g_Wl2s[160 * 480];
__device__ __align__(16) __nv_bfloat16 g_W2s[160 * 480];

// ---------------------------------------------------------------------------
// Weight split kernel: fp32 W[k][n] -> B-side triplets (+ padded vectors)
// ---------------------------------------------------------------------------
__global__ void split_w(const float* __restrict__ sW1,
                        const float* __restrict__ aW1,
                        const float* __restrict__ aW2,
                        const float* __restrict__ sW2,
                        const float* __restrict__ sW3,
                        const float* __restrict__ sb2,
                        const float* __restrict__ aW3,
                        const float* __restrict__ ab2)
{
    int idx = blockIdx.x * 256 + threadIdx.x;
    float e[8];
    __nv_bfloat16* dst;

    if (idx < 61440) {                  // g_W1s: 3 tiles, K=1024
        int t = idx / 20480, r = idx % 20480;
        int kg = r / 160, n = r % 160;
#pragma unroll
        for (int q = 0; q < 8; q++) {
            int k = kg * 8 + q;
            float v = 0.f;
            if (n < Hdim)
                v = (t == 0) ? sW1[(size_t)k * Hdim + n]
                  : (t == 1) ? sW1[(size_t)(1024 + k) * Hdim + n]
                             : aW1[(size_t)k * Hdim + n];
            e[q] = v;
        }
        dst = g_W1s + ((size_t)t * 160 + n) * 3072 + kg * 24;
    } else if (idx < 71680) {           // g_WCs: K=512
        int r = idx - 61440;
        int kg = r / 160, n = r % 160;
#pragma unroll
        for (int q = 0; q < 8; q++) {
            int k = kg * 8 + q;
            e[q] = (n < Hdim) ? sW1[(size_t)(2048 + k) * Hdim + n] : 0.f;
        }
        dst = g_WCs + (size_t)n * 1536 + kg * 24;
    } else if (idx < 74880) {           // g_Wl2s
        int r = idx - 71680;
        int kg = r / 160, n = r % 160;
#pragma unroll
        for (int q = 0; q < 8; q++) {
            int k = kg * 8 + q;
            e[q] = (n < Hdim && k < Hdim) ? aW2[(size_t)k * Hdim + n] : 0.f;
        }
        dst = g_Wl2s + (size_t)n * 480 + kg * 24;
    } else if (idx < 78080) {           // g_W2s
        int r = idx - 74880;
        int kg = r / 160, n = r % 160;
#pragma unroll
        for (int q = 0; q < 8; q++) {
            int k = kg * 8 + q;
            e[q] = (n < Hdim && k < Hdim) ? sW2[(size_t)k * Hdim + n] : 0.f;
        }
        dst = g_W2s + (size_t)n * 480 + kg * 24;
    } else if (idx < 78240) {
        int c = idx - 78080;
        g_sW3p[c] = (c < Hdim) ? sW3[c] : 0.f;
        g_sb2p[c] = (c < Hdim) ? sb2[c] : 0.f;
        return;
    } else if (idx < 78400) {
        int c = idx - 78240;
        g_aW3p[c] = (c < Hdim) ? aW3[c] : 0.f;
        g_ab2p[c] = (c < Hdim) ? ab2[c] : 0.f;
        return;
    } else return;

    __align__(16) __nv_bfloat16 t24[24];
#pragma unroll
    for (int q = 0; q < 8; q++) {
        __nv_bfloat16 h = __float2bfloat16(e[q]);
        __nv_bfloat16 l = __float2bfloat16(e[q] - __bfloat162float(h));
        t24[3 * q] = h; t24[3 * q + 1] = h; t24[3 * q + 2] = l;
    }
    uint4* d4 = (uint4*)dst;
    const uint4* s4 = (const uint4*)t24;
    d4[0] = s4[0]; d4[1] = s4[1]; d4[2] = s4[2];
}

// ---------------------------------------------------------------------------
// Tensor-core GEMM. BM = 32*MI, 320 threads = 10 warps (2m x 5n).
// NEW pipeline: ping-pong register sets + store-before-MMA + 1 barrier/chunk.
// ---------------------------------------------------------------------------
template<int MI, int MINB>
__global__ __launch_bounds__(320, MINB)
void mma_main(int job, const float* __restrict__ bias,
              const float* __restrict__ sc, float* __restrict__ outv,
              const float* __restrict__ Xf32)
{
    constexpr int BMt  = 32 * MI;
    constexpr int NA   = (BMt * 6 + 319) / 320;   // triplet-A uint4
    constexpr int NA32 = (BMt * 4 + 319) / 320;   // fp32-A float4
    extern __shared__ char smx[];
    __nv_bfloat16* Ab[2] = {(__nv_bfloat16*)smx,
                            (__nv_bfloat16*)smx + BMt * 56};
    __nv_bfloat16* Bb[2] = {(__nv_bfloat16*)smx + 2 * BMt * 56,
                            (__nv_bfloat16*)smx + 2 * BMt * 56 + 8960};
    float* red = (float*)(smx + (2 * BMt * 56 + 17920) * 2);

    const __nv_bfloat16 *Asrc = nullptr, *Wsrc;
    const float* Asrc32 = nullptr;
    int lda32 = 0;
    int nch, mode, Tmax = 0;
    int Kp;
    float* dst = nullptr;
    const float *wvec = nullptr, *bvec = nullptr;
    if (job == 0) {
        int y = blockIdx.y;
        if (y < 3) {
            Asrc32 = Xf32; lda32 = Sdim; Kp = 3072; nch = 64;
            Wsrc = g_W1s + (size_t)y * 160 * 3072;
            if (y == 0)      { dst = g_A; mode = 0; }
            else if (y == 1) { dst = g_B; mode = 0; }
            else             { mode = 3; }
        } else {
            Asrc32 = outv;  // embeds passed via outv slot for job0
            lda32 = Edim; Kp = 1536; nch = 32; Wsrc = g_WCs; dst = g_C; mode = 0;
        }
    } else if (job == 2) {
        Asrc = g_H1s; Kp = 480; nch = 10; Wsrc = g_Wl2s; mode = 2;
        wvec = g_aW3p; bvec = g_ab2p; dst = g_attn; Tmax = Ldim;
    } else {
        Asrc32 = g_X; lda32 = HP; Kp = 480; nch = 10; Wsrc = g_W2s; mode = 2;
        wvec = g_sW3p; bvec = g_sb2p; dst = outv; Tmax = Ttot;
    }
    const bool a32 = (Asrc32 != nullptr);

    const int tid  = threadIdx.x;
    const int lane = tid & 31;
    const int w    = tid >> 5;
    const int wm   = w / 5;
    const int wn   = w % 5;
    const int g    = lane >> 2;
    const int tg   = lane & 3;
    const int row0 = blockIdx.x * BMt;
    const int abase = (wm * 16 * MI + g) * 28 + tg;
    const int bbase = (wn * 32 + g) * 28 + tg;

    float acc[MI][4][4];
#pragma unroll
    for (int i = 0; i < MI; i++)
#pragma unroll
        for (int j = 0; j < 4; j++)
#pragma unroll
            for (int k = 0; k < 4; k++) acc[i][j][k] = 0.f;

    // ping-pong register sets
    uint4 rA[2][NA], rB[2][3];
    float4 fA[2][NA32];

    auto loadAB = [&](int ch, int s) {
        if (a32) {
#pragma unroll
            for (int it = 0; it < NA32; it++) {
                int idx = tid + it * 320;
                if (idx < BMt * 4) {
                    int m = idx >> 2, q = idx & 3;
                    fA[s][it] = *(const float4*)(Asrc32 + (size_t)(row0 + m) * lda32
                                                 + ch * 16 + q * 4);
                }
            }
        } else {
#pragma unroll
            for (int it = 0; it < NA; it++) {
                int idx = tid + it * 320;
                if (idx < BMt * 6) {
                    int m = idx / 6, q = idx - 6 * m;
                    rA[s][it] = *(const uint4*)(Asrc + (size_t)(row0 + m) * Kp
                                                + ch * 48 + q * 8);
                }
            }
        }
#pragma unroll
        for (int it = 0; it < 3; it++) {
            int idx = tid + it * 320;
            int n = idx / 6, q = idx - 6 * n;
            rB[s][it] = *(const uint4*)(Wsrc + (size_t)n * Kp + ch * 48 + q * 8);
        }
    };
    auto storeAB = [&](int pp, int s) {
        if (a32) {
#pragma unroll
            for (int it = 0; it < NA32; it++) {
                int idx = tid + it * 320;
                if (idx < BMt * 4) {
                    int m = idx >> 2, q = idx & 3;
                    float e[4] = {fA[s][it].x, fA[s][it].y, fA[s][it].z, fA[s][it].w};
                    __align__(8) __nv_bfloat16 t[12];
#pragma unroll
                    for (int i2 = 0; i2 < 4; i2++) {
                        __nv_bfloat16 h = __float2bfloat16(e[i2]);
                        __nv_bfloat16 l = __float2bfloat16(e[i2] - __bfloat162float(h));
                        t[3 * i2] = h; t[3 * i2 + 1] = l; t[3 * i2 + 2] = h;
                    }
                    uint2* d = (uint2*)(Ab[pp] + m * 56 + q * 12);
                    const uint2* ss = (const uint2*)t;
                    d[0] = ss[0]; d[1] = ss[1]; d[2] = ss[2];
                }
            }
        } else {
#pragma unroll
            for (int it = 0; it < NA; it++) {
                int idx = tid + it * 320;
                if (idx < BMt * 6) {
                    int m = idx / 6, q = idx - 6 * m;
                    *(uint4*)(Ab[pp] + m * 56 + q * 8) = rA[s][it];
                }
            }
        }
#pragma unroll
        for (int it = 0; it < 3; it++) {
            int idx = tid + it * 320;
            int n = idx / 6, q = idx - 6 * n;
            *(uint4*)(Bb[pp] + n * 56 + q * 8) = rB[s][it];
        }
    };
    auto domma = [&](int pp) {
        const unsigned* As32 = (const unsigned*)Ab[pp];
        const unsigned* Bs32 = (const unsigned*)Bb[pp];
#pragma unroll
        for (int st = 0; st < 3; st++) {
            const int ko = st * 8;
            unsigned b0[4], b1[4];
#pragma unroll
            for (int j = 0; j < 4; j++) {
                b0[j] = Bs32[bbase + j * 224 + ko];
                b1[j] = Bs32[bbase + j * 224 + ko + 4];
            }
#pragma unroll
            for (int i = 0; i < MI; i++) {
                unsigned a0 = As32[abase + i * 448 + ko];
                unsigned a1 = As32[abase + i * 448 + 224 + ko];
                unsigned a2 = As32[abase + i * 448 + ko + 4];
                unsigned a3 = As32[abase + i * 448 + 224 + ko + 4];
#pragma unroll
                for (int j = 0; j < 4; j++) {
                    asm volatile(
                        "mma.sync.aligned.m16n8k16.row.col.f32.bf16.bf16.f32 "
                        "{%0,%1,%2,%3},{%4,%5,%6,%7},{%8,%9},{%0,%1,%2,%3};"
                        : "+f"(acc[i][j][0]), "+f"(acc[i][j][1]),
                          "+f"(acc[i][j][2]), "+f"(acc[i][j][3])
                        : "r"(a0), "r"(a1), "r"(a2), "r"(a3),
                          "r"(b0[j]), "r"(b1[j]));
                }
            }
        }
    };

    // --- pipelined mainloop: 1 barrier/chunk, store overlapped with MMA ---
    loadAB(0, 0);
    storeAB(0, 0);                 // prologue fill (stalls once on load return)
    if (nch > 1) loadAB(1, 1);
    __syncthreads();
    int p = 0;
    for (int ch = 0; ch < nch; ch++) {
        if (ch + 2 < nch) loadAB(ch + 2, ch & 1);       // into freed set
        if (ch + 1 < nch) storeAB(p ^ 1, (ch + 1) & 1); // regs landed last iter
        domma(p);
        __syncthreads();
        p ^= 1;
    }

    if (mode == 0) {
#pragma unroll
        for (int i = 0; i < MI; i++) {
            int r = row0 + wm * 16 * MI + i * 16 + g;
#pragma unroll
            for (int j = 0; j < 4; j++) {
                int c = wn * 32 + j * 8 + 2 * tg;
                if (c < Hdim) {
                    dst[(size_t)r * HP + c]           = acc[i][j][0];
                    dst[(size_t)r * HP + c + 1]       = acc[i][j][1];
                    dst[(size_t)(r + 8) * HP + c]     = acc[i][j][2];
                    dst[(size_t)(r + 8) * HP + c + 1] = acc[i][j][3];
                }
            }
        }
    } else if (mode == 3) {
#pragma unroll
        for (int i = 0; i < MI; i++) {
            int r = row0 + wm * 16 * MI + i * 16 + g;
#pragma unroll
            for (int j = 0; j < 4; j++) {
                int c = wn * 32 + j * 8 + 2 * tg;
                if (c < Hdim) {
                    float b0 = bias[c], b1 = bias[c + 1];
                    float v0 = fmaxf(acc[i][j][0] + b0, 0.f);
                    float v1 = fmaxf(acc[i][j][1] + b1, 0.f);
                    float v2 = fmaxf(acc[i][j][2] + b0, 0.f);
                    float v3 = fmaxf(acc[i][j][3] + b1, 0.f);
#pragma unroll
                    for (int hh = 0; hh < 2; hh++) {
                        float va = hh ? v2 : v0, vb = hh ? v3 : v1;
                        int rr = r + 8 * hh;
                        __nv_bfloat16 ha = __float2bfloat16(va);
                        __nv_bfloat16 la = __float2bfloat16(va - __bfloat162float(ha));
                        __nv_bfloat16 hb = __float2bfloat16(vb);
                        __nv_bfloat16 lb = __float2bfloat16(vb - __bfloat162float(hb));
                        __nv_bfloat162* pt =
                            (__nv_bfloat162*)(g_H1s + (size_t)rr * 480 + 3 * c);
                        pt[0] = __nv_bfloat162{ha, la};
                        pt[1] = __nv_bfloat162{ha, hb};
                        pt[2] = __nv_bfloat162{lb, hb};
                    }
                }
            }
        }
    } else {
#pragma unroll
        for (int i = 0; i < MI; i++) {
            float pl = 0.f, ph = 0.f;
#pragma unroll
            for (int j = 0; j < 4; j++) {
                int c = wn * 32 + j * 8 + 2 * tg;
                float w0 = wvec[c], w1 = wvec[c + 1];
                float s0 = bvec[c], s1 = bvec[c + 1];
                pl += w0 * fmaxf(acc[i][j][0] + s0, 0.f)
                    + w1 * fmaxf(acc[i][j][1] + s1, 0.f);
                ph += w0 * fmaxf(acc[i][j][2] + s0, 0.f)
                    + w1 * fmaxf(acc[i][j][3] + s1, 0.f);
            }
            pl += __shfl_xor_sync(0xffffffffu, pl, 1);
            pl += __shfl_xor_sync(0xffffffffu, pl, 2);
            ph += __shfl_xor_sync(0xffffffffu, ph, 1);
            ph += __shfl_xor_sync(0xffffffffu, ph, 2);
            if (tg == 0) {
                int rl = wm * 16 * MI + i * 16 + g;
                red[rl * 5 + wn]       = pl;
                red[(rl + 8) * 5 + wn] = ph;
            }
        }
        __syncthreads();
        if (tid < BMt) {
            float s = sc[0];
#pragma unroll
            for (int q = 0; q < 5; q++) s += red[tid * 5 + q];
            int t = row0 + tid;
            if (t < Tmax) dst[t] = s;
        }
    }
}

// ---------------------------------------------------------------------------
// Pool: block = 8 starts x ALL 10 n; 256 threads (8 warps, 10 rows each).
// ---------------------------------------------------------------------------
__global__ __launch_bounds__(256)
void pool_kernel(const float* __restrict__ sb1)
{
    __shared__ float As[8][152];
    __shared__ float Bs[17][152];
    __shared__ float Cs[17][152];
    __shared__ float attw[24];
    __shared__ float sb1s[160];

    const int tid = threadIdx.x;
    const int s0  = blockIdx.x * 8;

    if (tid < 160) sb1s[tid] = (tid < Hdim) ? sb1[tid] : 0.f;
    if (tid >= 160 && tid < 177) {
        int i = tid - 160;
        int gg = s0 + i;
        attw[i] = (gg < Ldim) ? g_attn[gg] : 0.f;
    }
    for (int i = tid; i < 8 * 38; i += 256) {
        int r = i / 38, q = i % 38;
        *(float4*)&As[r][q * 4] = *(const float4*)(g_A + (size_t)(s0 + r) * HP + q * 4);
    }
    for (int i = tid; i < 17 * 38; i += 256) {
        int r = i / 38, q = i % 38;
        int gr = s0 + r;
        float4 v = make_float4(0.f, 0.f, 0.f, 0.f);
        if (gr < Ldim) v = *(const float4*)(g_B + (size_t)gr * HP + q * 4);
        *(float4*)&Bs[r][q * 4] = v;
    }
    for (int i = tid; i < 17 * 38; i += 256) {
        int r = i / 38, q = i % 38;
        int gr = s0 + r;
        float4 v = make_float4(0.f, 0.f, 0.f, 0.f);
        if (gr < Ldim) v = *(const float4*)(g_C + (size_t)gr * HP + q * 4);
        *(float4*)&Cs[r][q * 4] = v;
    }
    __syncthreads();

    const int warp = tid >> 5, lane = tid & 31;
#pragma unroll
    for (int rowi = warp; rowi < 80; rowi += 8) {
        const int n     = (rowi >> 3) + 1;
        const int si    = rowi & 7;
        const int start = s0 + si;
        if (start >= Ldim - n + 1) continue;    // warp-uniform

        float wj[MAXN];
        float mx = -1e30f;
        for (int j = 0; j < n; j++) mx = fmaxf(mx, attw[si + j]);
        float ssum = 0.f;
        for (int j = 0; j < n; j++) {
            float e = __expf(attw[si + j] - mx);
            wj[j] = e; ssum += e;
        }
        float inv = 1.f / ssum;

        const int off = (n - 1) * (Ldim + 1) - (n * (n - 1)) / 2;
        float* outp = g_X + (size_t)(off + start) * HP;
#pragma unroll
        for (int k = 0; k < 5; k++) {
            int c = lane + 32 * k;
            if (c < Hdim) {
                float pool = 0.f;
                for (int j = 0; j < n; j++) pool += wj[j] * Cs[si + j][c];
                float v = As[si][c] + Bs[si + n - 1][c] + sb1s[c] + pool * inv;
                outp[c] = fmaxf(v, 0.f);
            }
        }
    }
}

// ---------------------------------------------------------------------------
extern "C" void kernel_launch(void* const* d_in, const int* in_sizes, int n_in,
                              void* d_out, int out_size)
{
    const float* embeds = (const float*)d_in[0];
    const float* states = (const float*)d_in[1];
    const float* aW1    = (const float*)d_in[2];
    const float* ab1    = (const float*)d_in[3];
    const float* aW2    = (const float*)d_in[4];
    const float* ab2    = (const float*)d_in[5];
    const float* aW3    = (const float*)d_in[6];
    const float* ab3    = (const float*)d_in[7];
    const float* sW1    = (const float*)d_in[8];
    const float* sb1    = (const float*)d_in[9];
    const float* sW2    = (const float*)d_in[10];
    const float* sb2    = (const float*)d_in[11];
    const float* sW3    = (const float*)d_in[12];
    const float* sb3    = (const float*)d_in[13];
    float* out = (float*)d_out;

    cudaFuncSetAttribute(mma_main<4, 1>,
                         cudaFuncAttributeMaxDynamicSharedMemorySize, 67072);
    cudaFuncSetAttribute(mma_main<1, 3>,
                         cudaFuncAttributeMaxDynamicSharedMemorySize, 43648);
    cudaFuncSetAttribute(mma_main<2, 2>,
                         cudaFuncAttributeMaxDynamicSharedMemorySize, 51456);

    // weight splits + padded vectors (activations read fp32 directly)
    split_w<<<307, 256>>>(sW1, aW1, aW2, sW2, sW3, sb2, aW3, ab2);
    // precompute GEMMs: g_A, g_B, H1-triplets, g_C (BM=128, fp32 A staging)
    mma_main<4, 1><<<dim3(32, 4), 320, 67072>>>(0, ab1, nullptr,
                                                const_cast<float*>(embeds), states);
    // attn layer2 + layer3 fused -> g_attn  (BM=32, grid 128)
    mma_main<1, 3><<<dim3(128, 1), 320, 43648>>>(2, nullptr, ab3, nullptr, nullptr);
    // pooled rows (fp32) -> g_X  (8 starts x all n per block, grid 512)
    pool_kernel<<<512, 256>>>(sb1);
    // big GEMM (fp32 A staged->triplets) + fused layer3 -> out (BM=64, grid 640)
    mma_main<2, 2><<<dim3(640, 1), 320, 51456>>>(3, nullptr, sb3, out, nullptr);
}

// round 15
// speedup vs baseline: 2.3408x; 2.3408x over previous
#include <cuda_runtime.h>
#include <cuda_bf16.h>
#include <math.h>

#define Ldim 4096
#define Edim 512
#define Sdim 1024
#define Hdim 150
#define HP   160
#define MAXN 10
#define Ttot 40915
#define TP   40960

// ---------------------------------------------------------------------------
// Device scratch (zero-init; pad regions never written -> stay zero)
// ---------------------------------------------------------------------------
__device__ float g_A[Ldim * HP];
__device__ float g_B[Ldim * HP];
__device__ float g_C[Ldim * HP];
__device__ float g_attn[Ldim];
__device__ float g_X[(size_t)TP * HP];   // pooled rows, fp32 (pad cols stay 0)
__device__ float g_sW3p[HP];
__device__ float g_sb2p[HP];
__device__ float g_aW3p[HP];
__device__ float g_ab2p[HP];

// bf16 hi/lo triplet buffers.  A-side slot pattern: [xh, xl, xh]
//                              B-side slot pattern: [bh, bh, bl]
__device__ __align__(16) __nv_bfloat16 g_H1s[(size_t)Ldim * 480];
__device__ __align__(16) __nv_bfloat16 g_W1s[3 * 160 * 3072];
__device__ __align__(16) __nv_bfloat16 g_WCs[160 * 1536];
__device__ __align__(16) __nv_bfloat16 g_Wl2s[160 * 480];
__device__ __align__(16) __nv_bfloat16 g_W2s[160 * 480];

// ---------------------------------------------------------------------------
// Weight split kernel: fp32 W[k][n] -> B-side triplets (+ padded vectors)
// ---------------------------------------------------------------------------
__global__ void split_w(const float* __restrict__ sW1,
                        const float* __restrict__ aW1,
                        const float* __restrict__ aW2,
                        const float* __restrict__ sW2,
                        const float* __restrict__ sW3,
                        const float* __restrict__ sb2,
                        const float* __restrict__ aW3,
                        const float* __restrict__ ab2)
{
    int idx = blockIdx.x * 256 + threadIdx.x;
    float e[8];
    __nv_bfloat16* dst;

    if (idx < 61440) {                  // g_W1s: 3 tiles, K=1024
        int t = idx / 20480, r = idx % 20480;
        int kg = r / 160, n = r % 160;
#pragma unroll
        for (int q = 0; q < 8; q++) {
            int k = kg * 8 + q;
            float v = 0.f;
            if (n < Hdim)
                v = (t == 0) ? sW1[(size_t)k * Hdim + n]
                  : (t == 1) ? sW1[(size_t)(1024 + k) * Hdim + n]
                             : aW1[(size_t)k * Hdim + n];
            e[q] = v;
        }
        dst = g_W1s + ((size_t)t * 160 + n) * 3072 + kg * 24;
    } else if (idx < 71680) {           // g_WCs: K=512
        int r = idx - 61440;
        int kg = r / 160, n = r % 160;
#pragma unroll
        for (int q = 0; q < 8; q++) {
            int k = kg * 8 + q;
            e[q] = (n < Hdim) ? sW1[(size_t)(2048 + k) * Hdim + n] : 0.f;
        }
        dst = g_WCs + (size_t)n * 1536 + kg * 24;
    } else if (idx < 74880) {           // g_Wl2s
        int r = idx - 71680;
        int kg = r / 160, n = r % 160;
#pragma unroll
        for (int q = 0; q < 8; q++) {
            int k = kg * 8 + q;
            e[q] = (n < Hdim && k < Hdim) ? aW2[(size_t)k * Hdim + n] : 0.f;
        }
        dst = g_Wl2s + (size_t)n * 480 + kg * 24;
    } else if (idx < 78080) {           // g_W2s
        int r = idx - 74880;
        int kg = r / 160, n = r % 160;
#pragma unroll
        for (int q = 0; q < 8; q++) {
            int k = kg * 8 + q;
            e[q] = (n < Hdim && k < Hdim) ? sW2[(size_t)k * Hdim + n] : 0.f;
        }
        dst = g_W2s + (size_t)n * 480 + kg * 24;
    } else if (idx < 78240) {
        int c = idx - 78080;
        g_sW3p[c] = (c < Hdim) ? sW3[c] : 0.f;
        g_sb2p[c] = (c < Hdim) ? sb2[c] : 0.f;
        return;
    } else if (idx < 78400) {
        int c = idx - 78240;
        g_aW3p[c] = (c < Hdim) ? aW3[c] : 0.f;
        g_ab2p[c] = (c < Hdim) ? ab2[c] : 0.f;
        return;
    } else return;

    __align__(16) __nv_bfloat16 t24[24];
#pragma unroll
    for (int q = 0; q < 8; q++) {
        __nv_bfloat16 h = __float2bfloat16(e[q]);
        __nv_bfloat16 l = __float2bfloat16(e[q] - __bfloat162float(h));
        t24[3 * q] = h; t24[3 * q + 1] = h; t24[3 * q + 2] = l;
    }
    uint4* d4 = (uint4*)dst;
    const uint4* s4 = (const uint4*)t24;
    d4[0] = s4[0]; d4[1] = s4[1]; d4[2] = s4[2];
}

// ---------------------------------------------------------------------------
// Tensor-core GEMM. BM = 32*MI, 320 threads = 10 warps (2m x 5n).
// Pipelined: named ping-pong register sets (NO runtime indexing),
// store-before-MMA, 1 barrier/chunk. JOB is compile-time.
// ---------------------------------------------------------------------------
template<int MI, int MINB, int JOB>
__global__ __launch_bounds__(320, MINB)
void mma_main(const float* __restrict__ bias,
              const float* __restrict__ sc, float* __restrict__ outv,
              const float* __restrict__ Xf32)
{
    constexpr int BMt  = 32 * MI;
    constexpr int NA   = (BMt * 6 + 319) / 320;   // triplet-A uint4
    constexpr int NA32 = (BMt * 4 + 319) / 320;   // fp32-A float4
    constexpr bool a32 = (JOB != 2);
    extern __shared__ char smx[];
    __nv_bfloat16* Ab0 = (__nv_bfloat16*)smx;
    __nv_bfloat16* Ab1 = (__nv_bfloat16*)smx + BMt * 56;
    __nv_bfloat16* Bb0 = (__nv_bfloat16*)smx + 2 * BMt * 56;
    __nv_bfloat16* Bb1 = (__nv_bfloat16*)smx + 2 * BMt * 56 + 8960;
    float* red = (float*)(smx + (2 * BMt * 56 + 17920) * 2);

    const __nv_bfloat16 *Asrc = nullptr, *Wsrc;
    const float* Asrc32 = nullptr;
    int lda32 = 0;
    int nch, mode, Tmax = 0;
    int Kp;
    float* dst = nullptr;
    const float *wvec = nullptr, *bvec = nullptr;
    if (JOB == 0) {
        int y = blockIdx.y;
        if (y < 3) {
            Asrc32 = Xf32; lda32 = Sdim; Kp = 3072; nch = 64;
            Wsrc = g_W1s + (size_t)y * 160 * 3072;
            if (y == 0)      { dst = g_A; mode = 0; }
            else if (y == 1) { dst = g_B; mode = 0; }
            else             { mode = 3; }
        } else {
            Asrc32 = outv;  // embeds passed via outv slot for job0
            lda32 = Edim; Kp = 1536; nch = 32; Wsrc = g_WCs; dst = g_C; mode = 0;
        }
    } else if (JOB == 2) {
        Asrc = g_H1s; Kp = 480; nch = 10; Wsrc = g_Wl2s; mode = 2;
        wvec = g_aW3p; bvec = g_ab2p; dst = g_attn; Tmax = Ldim;
    } else {
        Asrc32 = g_X; lda32 = HP; Kp = 480; nch = 10; Wsrc = g_W2s; mode = 2;
        wvec = g_sW3p; bvec = g_sb2p; dst = outv; Tmax = Ttot;
    }

    const int tid  = threadIdx.x;
    const int lane = tid & 31;
    const int w    = tid >> 5;
    const int wm   = w / 5;
    const int wn   = w % 5;
    const int g    = lane >> 2;
    const int tg   = lane & 3;
    const int row0 = blockIdx.x * BMt;
    const int abase = (wm * 16 * MI + g) * 28 + tg;
    const int bbase = (wn * 32 + g) * 28 + tg;

    float acc[MI][4][4];
#pragma unroll
    for (int i = 0; i < MI; i++)
#pragma unroll
        for (int j = 0; j < 4; j++)
#pragma unroll
            for (int k = 0; k < 4; k++) acc[i][j][k] = 0.f;

    // named ping-pong register sets (static — stay in registers)
    uint4 rA_a[NA], rA_b[NA], rB_a[3], rB_b[3];
    float4 fA_a[NA32], fA_b[NA32];

#define LOADAB(ch, S) do {                                                     \
    if (a32) {                                                                 \
        _Pragma("unroll")                                                      \
        for (int it = 0; it < NA32; it++) {                                    \
            int idx = tid + it * 320;                                          \
            if (idx < BMt * 4) {                                               \
                int m = idx >> 2, q = idx & 3;                                 \
                fA_##S[it] = *(const float4*)(Asrc32 +                         \
                    (size_t)(row0 + m) * lda32 + (ch) * 16 + q * 4);           \
            }                                                                  \
        }                                                                      \
    } else {                                                                   \
        _Pragma("unroll")                                                      \
        for (int it = 0; it < NA; it++) {                                      \
            int idx = tid + it * 320;                                          \
            if (idx < BMt * 6) {                                               \
                int m = idx / 6, q = idx - 6 * m;                              \
                rA_##S[it] = *(const uint4*)(Asrc +                            \
                    (size_t)(row0 + m) * Kp + (ch) * 48 + q * 8);              \
            }                                                                  \
        }                                                                      \
    }                                                                          \
    _Pragma("unroll")                                                          \
    for (int it = 0; it < 3; it++) {                                           \
        int idx = tid + it * 320;                                              \
        int n = idx / 6, q = idx - 6 * n;                                      \
        rB_##S[it] = *(const uint4*)(Wsrc + (size_t)n * Kp + (ch) * 48 + q * 8); \
    }                                                                          \
} while (0)

#define STOREAB(P, S) do {                                                     \
    if (a32) {                                                                 \
        _Pragma("unroll")                                                      \
        for (int it = 0; it < NA32; it++) {                                    \
            int idx = tid + it * 320;                                          \
            if (idx < BMt * 4) {                                               \
                int m = idx >> 2, q = idx & 3;                                 \
                float e0 = fA_##S[it].x, e1 = fA_##S[it].y;                    \
                float e2 = fA_##S[it].z, e3 = fA_##S[it].w;                    \
                float ee[4] = {e0, e1, e2, e3};                                \
                __align__(8) __nv_bfloat16 t[12];                              \
                _Pragma("unroll")                                              \
                for (int i2 = 0; i2 < 4; i2++) {                               \
                    __nv_bfloat16 h = __float2bfloat16(ee[i2]);                \
                    __nv_bfloat16 l =                                          \
                        __float2bfloat16(ee[i2] - __bfloat162float(h));        \
                    t[3 * i2] = h; t[3 * i2 + 1] = l; t[3 * i2 + 2] = h;       \
                }                                                              \
                uint2* d = (uint2*)(Ab##P + m * 56 + q * 12);                  \
                const uint2* ss = (const uint2*)t;                             \
                d[0] = ss[0]; d[1] = ss[1]; d[2] = ss[2];                      \
            }                                                                  \
        }                                                                      \
    } else {                                                                   \
        _Pragma("unroll")                                                      \
        for (int it = 0; it < NA; it++) {                                      \
            int idx = tid + it * 320;                                          \
            if (idx < BMt * 6) {                                               \
                int m = idx / 6, q = idx - 6 * m;                              \
                *(uint4*)(Ab##P + m * 56 + q * 8) = rA_##S[it];                \
            }                                                                  \
        }                                                                      \
    }                                                                          \
    _Pragma("unroll")                                                          \
    for (int it = 0; it < 3; it++) {                                           \
        int idx = tid + it * 320;                                              \
        int n = idx / 6, q = idx - 6 * n;                                      \
        *(uint4*)(Bb##P + n * 56 + q * 8) = rB_##S[it];                        \
    }                                                                          \
} while (0)

#define DOMMA(P) do {                                                          \
    const unsigned* As32 = (const unsigned*)Ab##P;                             \
    const unsigned* Bs32 = (const unsigned*)Bb##P;                             \
    _Pragma("unroll")                                                          \
    for (int st = 0; st < 3; st++) {                                           \
        const int ko = st * 8;                                                 \
        unsigned b0[4], b1[4];                                                 \
        _Pragma("unroll")                                                      \
        for (int j = 0; j < 4; j++) {                                          \
            b0[j] = Bs32[bbase + j * 224 + ko];                                \
            b1[j] = Bs32[bbase + j * 224 + ko + 4];                            \
        }                                                                      \
        _Pragma("unroll")                                                      \
        for (int i = 0; i < MI; i++) {                                         \
            unsigned a0 = As32[abase + i * 448 + ko];                          \
            unsigned a1 = As32[abase + i * 448 + 224 + ko];                    \
            unsigned a2 = As32[abase + i * 448 + ko + 4];                      \
            unsigned a3 = As32[abase + i * 448 + 224 + ko + 4];                \
            _Pragma("unroll")                                                  \
            for (int j = 0; j < 4; j++) {                                      \
                asm volatile(                                                  \
                    "mma.sync.aligned.m16n8k16.row.col.f32.bf16.bf16.f32 "     \
                    "{%0,%1,%2,%3},{%4,%5,%6,%7},{%8,%9},{%0,%1,%2,%3};"       \
                    : "+f"(acc[i][j][0]), "+f"(acc[i][j][1]),                  \
                      "+f"(acc[i][j][2]), "+f"(acc[i][j][3])                   \
                    : "r"(a0), "r"(a1), "r"(a2), "r"(a3),                      \
                      "r"(b0[j]), "r"(b1[j]));                                 \
            }                                                                  \
        }                                                                      \
    }                                                                          \
} while (0)

    // --- pipelined mainloop: nch is even for all jobs (64/32/10) ---
    LOADAB(0, a);
    STOREAB(0, a);          // prologue (stalls once)
    LOADAB(1, a);           // set a now holds chunk 1
    __syncthreads();
    for (int ch = 0; ch < nch; ch += 2) {
        if (ch + 2 < nch) LOADAB(ch + 2, b);
        STOREAB(1, a);                       // buf1 <- chunk ch+1 (regs landed)
        DOMMA(0);                            // chunk ch
        __syncthreads();
        if (ch + 3 < nch) LOADAB(ch + 3, a);
        if (ch + 2 < nch) STOREAB(0, b);     // buf0 <- chunk ch+2
        DOMMA(1);                            // chunk ch+1
        __syncthreads();
    }
#undef LOADAB
#undef STOREAB
#undef DOMMA

    if (mode == 0) {
#pragma unroll
        for (int i = 0; i < MI; i++) {
            int r = row0 + wm * 16 * MI + i * 16 + g;
#pragma unroll
            for (int j = 0; j < 4; j++) {
                int c = wn * 32 + j * 8 + 2 * tg;
                if (c < Hdim) {
                    dst[(size_t)r * HP + c]           = acc[i][j][0];
                    dst[(size_t)r * HP + c + 1]       = acc[i][j][1];
                    dst[(size_t)(r + 8) * HP + c]     = acc[i][j][2];
                    dst[(size_t)(r + 8) * HP + c + 1] = acc[i][j][3];
                }
            }
        }
    } else if (mode == 3) {
#pragma unroll
        for (int i = 0; i < MI; i++) {
            int r = row0 + wm * 16 * MI + i * 16 + g;
#pragma unroll
            for (int j = 0; j < 4; j++) {
                int c = wn * 32 + j * 8 + 2 * tg;
                if (c < Hdim) {
                    float b0 = bias[c], b1 = bias[c + 1];
                    float v0 = fmaxf(acc[i][j][0] + b0, 0.f);
                    float v1 = fmaxf(acc[i][j][1] + b1, 0.f);
                    float v2 = fmaxf(acc[i][j][2] + b0, 0.f);
                    float v3 = fmaxf(acc[i][j][3] + b1, 0.f);
#pragma unroll
                    for (int hh = 0; hh < 2; hh++) {
                        float va = hh ? v2 : v0, vb = hh ? v3 : v1;
                        int rr = r + 8 * hh;
                        __nv_bfloat16 ha = __float2bfloat16(va);
                        __nv_bfloat16 la = __float2bfloat16(va - __bfloat162float(ha));
                        __nv_bfloat16 hb = __float2bfloat16(vb);
                        __nv_bfloat16 lb = __float2bfloat16(vb - __bfloat162float(hb));
                        __nv_bfloat162* pt =
                            (__nv_bfloat162*)(g_H1s + (size_t)rr * 480 + 3 * c);
                        pt[0] = __nv_bfloat162{ha, la};
                        pt[1] = __nv_bfloat162{ha, hb};
                        pt[2] = __nv_bfloat162{lb, hb};
                    }
                }
            }
        }
    } else {
#pragma unroll
        for (int i = 0; i < MI; i++) {
            float pl = 0.f, ph = 0.f;
#pragma unroll
            for (int j = 0; j < 4; j++) {
                int c = wn * 32 + j * 8 + 2 * tg;
                float w0 = wvec[c], w1 = wvec[c + 1];
                float s0 = bvec[c], s1 = bvec[c + 1];
                pl += w0 * fmaxf(acc[i][j][0] + s0, 0.f)
                    + w1 * fmaxf(acc[i][j][1] + s1, 0.f);
                ph += w0 * fmaxf(acc[i][j][2] + s0, 0.f)
                    + w1 * fmaxf(acc[i][j][3] + s1, 0.f);
            }
            pl += __shfl_xor_sync(0xffffffffu, pl, 1);
            pl += __shfl_xor_sync(0xffffffffu, pl, 2);
            ph += __shfl_xor_sync(0xffffffffu, ph, 1);
            ph += __shfl_xor_sync(0xffffffffu, ph, 2);
            if (tg == 0) {
                int rl = wm * 16 * MI + i * 16 + g;
                red[rl * 5 + wn]       = pl;
                red[(rl + 8) * 5 + wn] = ph;
            }
        }
        __syncthreads();
        if (tid < BMt) {
            float s = sc[0];
#pragma unroll
            for (int q = 0; q < 5; q++) s += red[tid * 5 + q];
            int t = row0 + tid;
            if (t < Tmax) dst[t] = s;
        }
    }
}

// ---------------------------------------------------------------------------
// Pool: block = 8 starts x ALL 10 n; 256 threads (8 warps, 10 rows each).
// ---------------------------------------------------------------------------
__global__ __launch_bounds__(256)
void pool_kernel(const float* __restrict__ sb1)
{
    __shared__ float As[8][152];
    __shared__ float Bs[17][152];
    __shared__ float Cs[17][152];
    __shared__ float attw[24];
    __shared__ float sb1s[160];

    const int tid = threadIdx.x;
    const int s0  = blockIdx.x * 8;

    if (tid < 160) sb1s[tid] = (tid < Hdim) ? sb1[tid] : 0.f;
    if (tid >= 160 && tid < 177) {
        int i = tid - 160;
        int gg = s0 + i;
        attw[i] = (gg < Ldim) ? g_attn[gg] : 0.f;
    }
    for (int i = tid; i < 8 * 38; i += 256) {
        int r = i / 38, q = i % 38;
        *(float4*)&As[r][q * 4] = *(const float4*)(g_A + (size_t)(s0 + r) * HP + q * 4);
    }
    for (int i = tid; i < 17 * 38; i += 256) {
        int r = i / 38, q = i % 38;
        int gr = s0 + r;
        float4 v = make_float4(0.f, 0.f, 0.f, 0.f);
        if (gr < Ldim) v = *(const float4*)(g_B + (size_t)gr * HP + q * 4);
        *(float4*)&Bs[r][q * 4] = v;
    }
    for (int i = tid; i < 17 * 38; i += 256) {
        int r = i / 38, q = i % 38;
        int gr = s0 + r;
        float4 v = make_float4(0.f, 0.f, 0.f, 0.f);
        if (gr < Ldim) v = *(const float4*)(g_C + (size_t)gr * HP + q * 4);
        *(float4*)&Cs[r][q * 4] = v;
    }
    __syncthreads();

    const int warp = tid >> 5, lane = tid & 31;
#pragma unroll
    for (int rowi = warp; rowi < 80; rowi += 8) {
        const int n     = (rowi >> 3) + 1;
        const int si    = rowi & 7;
        const int start = s0 + si;
        if (start >= Ldim - n + 1) continue;    // warp-uniform

        float wj[MAXN];
        float mx = -1e30f;
        for (int j = 0; j < n; j++) mx = fmaxf(mx, attw[si + j]);
        float ssum = 0.f;
        for (int j = 0; j < n; j++) {
            float e = __expf(attw[si + j] - mx);
            wj[j] = e; ssum += e;
        }
        float inv = 1.f / ssum;

        const int off = (n - 1) * (Ldim + 1) - (n * (n - 1)) / 2;
        float* outp = g_X + (size_t)(off + start) * HP;
#pragma unroll
        for (int k = 0; k < 5; k++) {
            int c = lane + 32 * k;
            if (c < Hdim) {
                float pool = 0.f;
                for (int j = 0; j < n; j++) pool += wj[j] * Cs[si + j][c];
                float v = As[si][c] + Bs[si + n - 1][c] + sb1s[c] + pool * inv;
                outp[c] = fmaxf(v, 0.f);
            }
        }
    }
}

// ---------------------------------------------------------------------------
extern "C" void kernel_launch(void* const* d_in, const int* in_sizes, int n_in,
                              void* d_out, int out_size)
{
    const float* embeds = (const float*)d_in[0];
    const float* states = (const float*)d_in[1];
    const float* aW1    = (const float*)d_in[2];
    const float* ab1    = (const float*)d_in[3];
    const float* aW2    = (const float*)d_in[4];
    const float* ab2    = (const float*)d_in[5];
    const float* aW3    = (const float*)d_in[6];
    const float* ab3    = (const float*)d_in[7];
    const float* sW1    = (const float*)d_in[8];
    const float* sb1    = (const float*)d_in[9];
    const float* sW2    = (const float*)d_in[10];
    const float* sb2    = (const float*)d_in[11];
    const float* sW3    = (const float*)d_in[12];
    const float* sb3    = (const float*)d_in[13];
    float* out = (float*)d_out;

    cudaFuncSetAttribute(mma_main<4, 1, 0>,
                         cudaFuncAttributeMaxDynamicSharedMemorySize, 67072);
    cudaFuncSetAttribute(mma_main<1, 3, 2>,
                         cudaFuncAttributeMaxDynamicSharedMemorySize, 43648);
    cudaFuncSetAttribute(mma_main<2, 2, 3>,
                         cudaFuncAttributeMaxDynamicSharedMemorySize, 51456);

    // weight splits + padded vectors (activations read fp32 directly)
    split_w<<<307, 256>>>(sW1, aW1, aW2, sW2, sW3, sb2, aW3, ab2);
    // precompute GEMMs: g_A, g_B, H1-triplets, g_C (BM=128, fp32 A staging)
    mma_main<4, 1, 0><<<dim3(32, 4), 320, 67072>>>(ab1, nullptr,
                                                   const_cast<float*>(embeds), states);
    // attn layer2 + layer3 fused -> g_attn  (BM=32, grid 128)
    mma_main<1, 3, 2><<<dim3(128, 1), 320, 43648>>>(nullptr, ab3, nullptr, nullptr);
    // pooled rows (fp32) -> g_X  (8 starts x all n per block, grid 512)
    pool_kernel<<<512, 256>>>(sb1);
    // big GEMM (fp32 A staged->triplets) + fused layer3 -> out (BM=64, grid 640)
    mma_main<2, 2, 3><<<dim3(640, 1), 320, 51456>>>(nullptr, sb3, out, nullptr);
}

// round 17
// speedup vs baseline: 2.7424x; 1.1715x over previous
#include <cuda_runtime.h>
#include <cuda_bf16.h>
#include <cuda_fp16.h>
#include <math.h>

#define Ldim 4096
#define Edim 512
#define Sdim 1024
#define Hdim 150
#define HP   160
#define MAXN 10
#define Ttot 40915
#define TP   40960

// ---------------------------------------------------------------------------
// Device scratch (zero-init; pad regions never written -> stay zero)
// ---------------------------------------------------------------------------
__device__ float g_A[Ldim * HP];
__device__ float g_B[Ldim * HP];
__device__ float g_C[Ldim * HP];
__device__ float g_attn[Ldim];
__device__ float g_X[(size_t)TP * HP];
__device__ float g_sW3p[HP];
__device__ float g_sb2p[HP];
__device__ float g_aW3p[HP];
__device__ float g_ab2p[HP];

// job2 path (bf16 3-slot triplets): A=[xh,xl,xh], B=[bh,bh,bl]
__device__ __align__(16) __nv_bfloat16 g_H1s[(size_t)Ldim * 480];
__device__ __align__(16) __nv_bfloat16 g_Wl2s[160 * 480];

// fp16 dup-slot weights for main GEMMs: [n][k'], k' = 2k+s, both slots = bh.
// row lengths padded to chunk multiples (zeros beyond real K).
__device__ __align__(16) __half g_W1h[(size_t)3 * 160 * 2112];  // states GEMMs, 44 chunks
__device__ __align__(16) __half g_WCh[(size_t)160 * 1056];      // embeds GEMM, 22 chunks
__device__ __align__(16) __half g_W2h[(size_t)160 * 384];       // final GEMM,  8 chunks

// ---------------------------------------------------------------------------
// fp16 pack helpers
// ---------------------------------------------------------------------------
__device__ __forceinline__ unsigned hdup(float x) {
    __half h = __float2half(x);
    unsigned short us; __builtin_memcpy(&us, &h, 2);
    return (unsigned)us * 0x10001u;
}
__device__ __forceinline__ unsigned hsplit(float x) {
    __half h = __float2half(x);
    __half l = __float2half(x - __half2float(h));
    unsigned short a, b;
    __builtin_memcpy(&a, &h, 2); __builtin_memcpy(&b, &l, 2);
    return (unsigned)a | ((unsigned)b << 16);
}

// ---------------------------------------------------------------------------
// split_w: fp16 dup-slot weights + job2 bf16 triplets + padded vectors
// ---------------------------------------------------------------------------
__global__ void split_w(const float* __restrict__ sW1,
                        const float* __restrict__ aW1,
                        const float* __restrict__ aW2,
                        const float* __restrict__ sW2,
                        const float* __restrict__ sW3,
                        const float* __restrict__ sb2,
                        const float* __restrict__ aW3,
                        const float* __restrict__ ab2)
{
    int idx = blockIdx.x * 256 + threadIdx.x;

    if (idx < 126720) {                 // g_W1h: 3 tiles x 160 n x 264 groups
        int t = idx / 42240, r = idx % 42240;
        int n = r / 264, gq = r % 264;
        const float* base = (t == 2) ? aW1 : sW1;
        int rowoff = (t == 1) ? 1024 : 0;
        uint4 u;
        unsigned e[4];
#pragma unroll
        for (int q = 0; q < 4; q++) {
            int k = gq * 4 + q;
            float v = (n < Hdim && k < 1024) ? base[(size_t)(rowoff + k) * Hdim + n] : 0.f;
            e[q] = hdup(v);
        }
        u.x = e[0]; u.y = e[1]; u.z = e[2]; u.w = e[3];
        *(uint4*)(g_W1h + ((size_t)t * 160 + n) * 2112 + gq * 8) = u;
        return;
    }
    idx -= 126720;
    if (idx < 21120) {                  // g_WCh: 160 n x 132 groups
        int n = idx / 132, gq = idx % 132;
        uint4 u;
        unsigned e[4];
#pragma unroll
        for (int q = 0; q < 4; q++) {
            int k = gq * 4 + q;
            float v = (n < Hdim && k < 512) ? sW1[(size_t)(2048 + k) * Hdim + n] : 0.f;
            e[q] = hdup(v);
        }
        u.x = e[0]; u.y = e[1]; u.z = e[2]; u.w = e[3];
        *(uint4*)(g_WCh + (size_t)n * 1056 + gq * 8) = u;
        return;
    }
    idx -= 21120;
    if (idx < 7680) {                   // g_W2h: 160 n x 48 groups
        int n = idx / 48, gq = idx % 48;
        uint4 u;
        unsigned e[4];
#pragma unroll
        for (int q = 0; q < 4; q++) {
            int k = gq * 4 + q;
            float v = (n < Hdim && k < Hdim) ? sW2[(size_t)k * Hdim + n] : 0.f;
            e[q] = hdup(v);
        }
        u.x = e[0]; u.y = e[1]; u.z = e[2]; u.w = e[3];
        *(uint4*)(g_W2h + (size_t)n * 384 + gq * 8) = u;
        return;
    }
    idx -= 7680;
    if (idx < 3200) {                   // g_Wl2s (bf16 3-slot) for job2
        int kg = idx / 160, n = idx - kg * 160;
        float e[8];
#pragma unroll
        for (int q = 0; q < 8; q++) {
            int k = kg * 8 + q;
            e[q] = (n < Hdim && k < Hdim) ? aW2[(size_t)k * Hdim + n] : 0.f;
        }
        __align__(16) __nv_bfloat16 t24[24];
#pragma unroll
        for (int q = 0; q < 8; q++) {
            __nv_bfloat16 h = __float2bfloat16(e[q]);
            __nv_bfloat16 l = __float2bfloat16(e[q] - __bfloat162float(h));
            t24[3 * q] = h; t24[3 * q + 1] = h; t24[3 * q + 2] = l;
        }
        uint4* d4 = (uint4*)(g_Wl2s + (size_t)n * 480 + kg * 24);
        const uint4* s4 = (const uint4*)t24;
        d4[0] = s4[0]; d4[1] = s4[1]; d4[2] = s4[2];
        return;
    }
    idx -= 3200;
    if (idx < 160) {
        g_sW3p[idx] = (idx < Hdim) ? sW3[idx] : 0.f;
        g_sb2p[idx] = (idx < Hdim) ? sb2[idx] : 0.f;
        return;
    }
    idx -= 160;
    if (idx < 160) {
        g_aW3p[idx] = (idx < Hdim) ? aW3[idx] : 0.f;
        g_ab2p[idx] = (idx < Hdim) ? ab2[idx] : 0.f;
    }
}

// ---------------------------------------------------------------------------
// fp16 tensor-core GEMM. BM = 32*MI, 320 threads = 10 warps (2m x 5n).
// A: fp32 source, converted to [xh, xl] pairs during smem staging (k'=2k+s).
// B: pre-split dup-slot fp16 weights. Chunk = 48 k' = 24 real k.
// Pipeline: named ping-pong register sets, store-before-MMA, 1 barrier/chunk.
// ---------------------------------------------------------------------------
template<int MI, int MINB, int JOB>
__global__ __launch_bounds__(320, MINB)
void mma_main(const float* __restrict__ bias,
              const float* __restrict__ sc, float* __restrict__ outv,
              const float* __restrict__ Xf32)
{
    constexpr int BMt  = 32 * MI;
    constexpr int NA32 = (BMt * 6 + 319) / 320;   // fp32-A float4 per thread
    extern __shared__ char smx[];
    __half* Ab0 = (__half*)smx;
    __half* Ab1 = (__half*)smx + BMt * 56;
    __half* Bb0 = (__half*)smx + 2 * BMt * 56;
    __half* Bb1 = (__half*)smx + 2 * BMt * 56 + 8960;
    float* red = (float*)(smx + (2 * BMt * 56 + 17920) * 2);

    const __half* Wsrc;
    const float* Asrc32;
    int lda32, Klim, nch, Kp, mode, Tmax = 0;
    float* dst = nullptr;
    const float *wvec = nullptr, *bvec = nullptr;
    if (JOB == 0) {
        int y = blockIdx.y;
        if (y < 3) {
            Asrc32 = Xf32; lda32 = Sdim; Klim = Sdim; nch = 44; Kp = 2112;
            Wsrc = g_W1h + (size_t)y * 160 * 2112;
            if (y == 0)      { dst = g_A; mode = 0; }
            else if (y == 1) { dst = g_B; mode = 0; }
            else             { mode = 3; }
        } else {
            Asrc32 = outv;  // embeds passed via outv slot for job0
            lda32 = Edim; Klim = Edim; nch = 22; Kp = 1056;
            Wsrc = g_WCh; dst = g_C; mode = 0;
        }
    } else {
        Asrc32 = g_X; lda32 = HP; Klim = HP; nch = 8; Kp = 384;
        Wsrc = g_W2h; mode = 2;
        wvec = g_sW3p; bvec = g_sb2p; dst = outv; Tmax = Ttot;
    }

    const int tid  = threadIdx.x;
    const int lane = tid & 31;
    const int w    = tid >> 5;
    const int wm   = w / 5;
    const int wn   = w % 5;
    const int g    = lane >> 2;
    const int tg   = lane & 3;
    const int row0 = blockIdx.x * BMt;
    const int abase = (wm * 16 * MI + g) * 28 + tg;
    const int bbase = (wn * 32 + g) * 28 + tg;

    float acc[MI][4][4];
#pragma unroll
    for (int i = 0; i < MI; i++)
#pragma unroll
        for (int j = 0; j < 4; j++)
#pragma unroll
            for (int k = 0; k < 4; k++) acc[i][j][k] = 0.f;

    // named ping-pong register sets (static -> stay in registers)
    float4 fA_a[NA32], fA_b[NA32];
    uint4 rB_a[3], rB_b[3];

#define LOADAB(ch, S) do {                                                     \
    _Pragma("unroll")                                                          \
    for (int it = 0; it < NA32; it++) {                                        \
        int idx = tid + it * 320;                                              \
        if (idx < BMt * 6) {                                                   \
            int m = idx / 6, q = idx - 6 * m;                                  \
            int col = (ch) * 24 + q * 4;                                       \
            float4 v = make_float4(0.f, 0.f, 0.f, 0.f);                        \
            if (col < Klim)                                                    \
                v = *(const float4*)(Asrc32 + (size_t)(row0 + m) * lda32 + col); \
            fA_##S[it] = v;                                                    \
        }                                                                      \
    }                                                                          \
    _Pragma("unroll")                                                          \
    for (int it = 0; it < 3; it++) {                                           \
        int idx = tid + it * 320;                                              \
        int n = idx / 6, q = idx - 6 * n;                                      \
        rB_##S[it] = *(const uint4*)(Wsrc + (size_t)n * Kp + (ch) * 48 + q * 8); \
    }                                                                          \
} while (0)

#define STOREAB(P, S) do {                                                     \
    _Pragma("unroll")                                                          \
    for (int it = 0; it < NA32; it++) {                                        \
        int idx = tid + it * 320;                                              \
        if (idx < BMt * 6) {                                                   \
            int m = idx / 6, q = idx - 6 * m;                                  \
            uint4 u;                                                           \
            u.x = hsplit(fA_##S[it].x);                                        \
            u.y = hsplit(fA_##S[it].y);                                        \
            u.z = hsplit(fA_##S[it].z);                                        \
            u.w = hsplit(fA_##S[it].w);                                        \
            *(uint4*)(Ab##P + m * 56 + q * 8) = u;                             \
        }                                                                      \
    }                                                                          \
    _Pragma("unroll")                                                          \
    for (int it = 0; it < 3; it++) {                                           \
        int idx = tid + it * 320;                                              \
        int n = idx / 6, q = idx - 6 * n;                                      \
        *(uint4*)(Bb##P + n * 56 + q * 8) = rB_##S[it];                        \
    }                                                                          \
} while (0)

#define DOMMA(P) do {                                                          \
    const unsigned* As32 = (const unsigned*)Ab##P;                             \
    const unsigned* Bs32 = (const unsigned*)Bb##P;                             \
    _Pragma("unroll")                                                          \
    for (int st = 0; st < 3; st++) {                                           \
        const int ko = st * 8;                                                 \
        unsigned b0[4], b1[4];                                                 \
        _Pragma("unroll")                                                      \
        for (int j = 0; j < 4; j++) {                                          \
            b0[j] = Bs32[bbase + j * 224 + ko];                                \
            b1[j] = Bs32[bbase + j * 224 + ko + 4];                            \
        }                                                                      \
        _Pragma("unroll")                                                      \
        for (int i = 0; i < MI; i++) {                                         \
            unsigned a0 = As32[abase + i * 448 + ko];                          \
            unsigned a1 = As32[abase + i * 448 + 224 + ko];                    \
            unsigned a2 = As32[abase + i * 448 + ko + 4];                      \
            unsigned a3 = As32[abase + i * 448 + 224 + ko + 4];                \
            _Pragma("unroll")                                                  \
            for (int j = 0; j < 4; j++) {                                      \
                asm volatile(                                                  \
                    "mma.sync.aligned.m16n8k16.row.col.f32.f16.f16.f32 "       \
                    "{%0,%1,%2,%3},{%4,%5,%6,%7},{%8,%9},{%0,%1,%2,%3};"       \
                    : "+f"(acc[i][j][0]), "+f"(acc[i][j][1]),                  \
                      "+f"(acc[i][j][2]), "+f"(acc[i][j][3])                   \
                    : "r"(a0), "r"(a1), "r"(a2), "r"(a3),                      \
                      "r"(b0[j]), "r"(b1[j]));                                 \
            }                                                                  \
        }                                                                      \
    }                                                                          \
} while (0)

    // --- pipelined mainloop: nch even for all jobs (44/22/8) ---
    LOADAB(0, a);
    STOREAB(0, a);          // prologue (stalls once)
    LOADAB(1, a);           // set a now holds chunk 1
    __syncthreads();
    for (int ch = 0; ch < nch; ch += 2) {
        if (ch + 2 < nch) LOADAB(ch + 2, b);
        STOREAB(1, a);                       // buf1 <- chunk ch+1
        DOMMA(0);                            // chunk ch
        __syncthreads();
        if (ch + 3 < nch) LOADAB(ch + 3, a);
        if (ch + 2 < nch) STOREAB(0, b);     // buf0 <- chunk ch+2
        DOMMA(1);                            // chunk ch+1
        __syncthreads();
    }
#undef LOADAB
#undef STOREAB
#undef DOMMA

    if (mode == 0) {
#pragma unroll
        for (int i = 0; i < MI; i++) {
            int r = row0 + wm * 16 * MI + i * 16 + g;
#pragma unroll
            for (int j = 0; j < 4; j++) {
                int c = wn * 32 + j * 8 + 2 * tg;
                if (c < Hdim) {
                    dst[(size_t)r * HP + c]           = acc[i][j][0];
                    dst[(size_t)r * HP + c + 1]       = acc[i][j][1];
                    dst[(size_t)(r + 8) * HP + c]     = acc[i][j][2];
                    dst[(size_t)(r + 8) * HP + c + 1] = acc[i][j][3];
                }
            }
        }
    } else if (mode == 3) {
#pragma unroll
        for (int i = 0; i < MI; i++) {
            int r = row0 + wm * 16 * MI + i * 16 + g;
#pragma unroll
            for (int j = 0; j < 4; j++) {
                int c = wn * 32 + j * 8 + 2 * tg;
                if (c < Hdim) {
                    float b0 = bias[c], b1 = bias[c + 1];
                    float v0 = fmaxf(acc[i][j][0] + b0, 0.f);
                    float v1 = fmaxf(acc[i][j][1] + b1, 0.f);
                    float v2 = fmaxf(acc[i][j][2] + b0, 0.f);
                    float v3 = fmaxf(acc[i][j][3] + b1, 0.f);
#pragma unroll
                    for (int hh = 0; hh < 2; hh++) {
                        float va = hh ? v2 : v0, vb = hh ? v3 : v1;
                        int rr = r + 8 * hh;
                        __nv_bfloat16 ha = __float2bfloat16(va);
                        __nv_bfloat16 la = __float2bfloat16(va - __bfloat162float(ha));
                        __nv_bfloat16 hb = __float2bfloat16(vb);
                        __nv_bfloat16 lb = __float2bfloat16(vb - __bfloat162float(hb));
                        __nv_bfloat162* pt =
                            (__nv_bfloat162*)(g_H1s + (size_t)rr * 480 + 3 * c);
                        pt[0] = __nv_bfloat162{ha, la};
                        pt[1] = __nv_bfloat162{ha, hb};
                        pt[2] = __nv_bfloat162{lb, hb};
                    }
                }
            }
        }
    } else {
#pragma unroll
        for (int i = 0; i < MI; i++) {
            float pl = 0.f, ph = 0.f;
#pragma unroll
            for (int j = 0; j < 4; j++) {
                int c = wn * 32 + j * 8 + 2 * tg;
                float w0 = wvec[c], w1 = wvec[c + 1];
                float s0 = bvec[c], s1 = bvec[c + 1];
                pl += w0 * fmaxf(acc[i][j][0] + s0, 0.f)
                    + w1 * fmaxf(acc[i][j][1] + s1, 0.f);
                ph += w0 * fmaxf(acc[i][j][2] + s0, 0.f)
                    + w1 * fmaxf(acc[i][j][3] + s1, 0.f);
            }
            pl += __shfl_xor_sync(0xffffffffu, pl, 1);
            pl += __shfl_xor_sync(0xffffffffu, pl, 2);
            ph += __shfl_xor_sync(0xffffffffu, ph, 1);
            ph += __shfl_xor_sync(0xffffffffu, ph, 2);
            if (tg == 0) {
                int rl = wm * 16 * MI + i * 16 + g;
                red[rl * 5 + wn]       = pl;
                red[(rl + 8) * 5 + wn] = ph;
            }
        }
        __syncthreads();
        if (tid < BMt) {
            float s = sc[0];
#pragma unroll
            for (int q = 0; q < 5; q++) s += red[tid * 5 + q];
            int t = row0 + tid;
            if (t < Tmax) dst[t] = s;
        }
    }
}

// ---------------------------------------------------------------------------
// job2 (attn layer2+3) — bf16 3-slot mma.sync path, unchanged
// ---------------------------------------------------------------------------
__global__ __launch_bounds__(320, 3)
void mma_attn(const float* __restrict__ ab3)
{
    extern __shared__ char smx[];
    __nv_bfloat16* Ab0 = (__nv_bfloat16*)smx;
    __nv_bfloat16* Ab1 = (__nv_bfloat16*)smx + 1792;
    __nv_bfloat16* Bb0 = (__nv_bfloat16*)smx + 3584;
    __nv_bfloat16* Bb1 = (__nv_bfloat16*)smx + 12544;
    float* red = (float*)(smx + 43008);

    const int tid  = threadIdx.x;
    const int lane = tid & 31;
    const int w    = tid >> 5;
    const int wm   = w / 5;
    const int wn   = w % 5;
    const int g    = lane >> 2;
    const int tg   = lane & 3;
    const int row0 = blockIdx.x * 32;
    const int abase = (wm * 16 + g) * 28 + tg;
    const int bbase = (wn * 32 + g) * 28 + tg;

    float acc[4][4];
#pragma unroll
    for (int j = 0; j < 4; j++)
#pragma unroll
        for (int k = 0; k < 4; k++) acc[j][k] = 0.f;

    uint4 rA_a, rA_b, rB_a[3], rB_b[3];

#define LOADAB2(ch, S) do {                                                    \
    if (tid < 192) {                                                           \
        int mm = tid / 6, q = tid - 6 * mm;                                    \
        rA_##S = *(const uint4*)(g_H1s + (size_t)(row0 + mm) * 480 + (ch) * 48 + q * 8); \
    }                                                                          \
    _Pragma("unroll")                                                          \
    for (int it = 0; it < 3; it++) {                                           \
        int idx = tid + it * 320;                                              \
        int n = idx / 6, q = idx - 6 * n;                                      \
        rB_##S[it] = *(const uint4*)(g_Wl2s + (size_t)n * 480 + (ch) * 48 + q * 8); \
    }                                                                          \
} while (0)
#define STOREAB2(P, S) do {                                                    \
    if (tid < 192) {                                                           \
        int mm = tid / 6, q = tid - 6 * mm;                                    \
        *(uint4*)(Ab##P + mm * 56 + q * 8) = rA_##S;                           \
    }                                                                          \
    _Pragma("unroll")                                                          \
    for (int it = 0; it < 3; it++) {                                           \
        int idx = tid + it * 320;                                              \
        int n = idx / 6, q = idx - 6 * n;                                      \
        *(uint4*)(Bb##P + n * 56 + q * 8) = rB_##S[it];                        \
    }                                                                          \
} while (0)
#define DOMMA2(P) do {                                                         \
    const unsigned* As32 = (const unsigned*)Ab##P;                             \
    const unsigned* Bs32 = (const unsigned*)Bb##P;                             \
    _Pragma("unroll")                                                          \
    for (int st = 0; st < 3; st++) {                                           \
        const int ko = st * 8;                                                 \
        unsigned b0[4], b1[4];                                                 \
        _Pragma("unroll")                                                      \
        for (int j = 0; j < 4; j++) {                                          \
            b0[j] = Bs32[bbase + j * 224 + ko];                                \
            b1[j] = Bs32[bbase + j * 224 + ko + 4];                            \
        }                                                                      \
        unsigned a0 = As32[abase + ko];                                        \
        unsigned a1 = As32[abase + 224 + ko];                                  \
        unsigned a2 = As32[abase + ko + 4];                                    \
        unsigned a3 = As32[abase + 224 + ko + 4];                              \
        _Pragma("unroll")                                                      \
        for (int j = 0; j < 4; j++) {                                          \
            asm volatile(                                                      \
                "mma.sync.aligned.m16n8k16.row.col.f32.bf16.bf16.f32 "         \
                "{%0,%1,%2,%3},{%4,%5,%6,%7},{%8,%9},{%0,%1,%2,%3};"           \
                : "+f"(acc[j][0]), "+f"(acc[j][1]),                            \
                  "+f"(acc[j][2]), "+f"(acc[j][3])                             \
                : "r"(a0), "r"(a1), "r"(a2), "r"(a3),                          \
                  "r"(b0[j]), "r"(b1[j]));                                     \
        }                                                                      \
    }                                                                          \
} while (0)

    LOADAB2(0, a);
    STOREAB2(0, a);
    LOADAB2(1, a);
    __syncthreads();
    for (int ch = 0; ch < 10; ch += 2) {
        if (ch + 2 < 10) LOADAB2(ch + 2, b);
        STOREAB2(1, a);
        DOMMA2(0);
        __syncthreads();
        if (ch + 3 < 10) LOADAB2(ch + 3, a);
        if (ch + 2 < 10) STOREAB2(0, b);
        DOMMA2(1);
        __syncthreads();
    }
#undef LOADAB2
#undef STOREAB2
#undef DOMMA2

    {
        float pl = 0.f, ph = 0.f;
#pragma unroll
        for (int j = 0; j < 4; j++) {
            int c = wn * 32 + j * 8 + 2 * tg;
            float w0 = g_aW3p[c], w1 = g_aW3p[c + 1];
            float s0 = g_ab2p[c], s1 = g_ab2p[c + 1];
            pl += w0 * fmaxf(acc[j][0] + s0, 0.f) + w1 * fmaxf(acc[j][1] + s1, 0.f);
            ph += w0 * fmaxf(acc[j][2] + s0, 0.f) + w1 * fmaxf(acc[j][3] + s1, 0.f);
        }
        pl += __shfl_xor_sync(0xffffffffu, pl, 1);
        pl += __shfl_xor_sync(0xffffffffu, pl, 2);
        ph += __shfl_xor_sync(0xffffffffu, ph, 1);
        ph += __shfl_xor_sync(0xffffffffu, ph, 2);
        if (tg == 0) {
            int rl = wm * 16 + g;
            red[rl * 5 + wn]       = pl;
            red[(rl + 8) * 5 + wn] = ph;
        }
    }
    __syncthreads();
    if (tid < 32) {
        float s = ab3[0];
#pragma unroll
        for (int q = 0; q < 5; q++) s += red[tid * 5 + q];
        g_attn[row0 + tid] = s;
    }
}

// ---------------------------------------------------------------------------
// Pool (unchanged): block = 8 starts x ALL 10 n
// ---------------------------------------------------------------------------
__global__ __launch_bounds__(256)
void pool_kernel(const float* __restrict__ sb1)
{
    __shared__ float As[8][152];
    __shared__ float Bs[17][152];
    __shared__ float Cs[17][152];
    __shared__ float attw[24];
    __shared__ float sb1s[160];

    const int tid = threadIdx.x;
    const int s0  = blockIdx.x * 8;

    if (tid < 160) sb1s[tid] = (tid < Hdim) ? sb1[tid] : 0.f;
    if (tid >= 160 && tid < 177) {
        int i = tid - 160;
        int gg = s0 + i;
        attw[i] = (gg < Ldim) ? g_attn[gg] : 0.f;
    }
    for (int i = tid; i < 8 * 38; i += 256) {
        int r = i / 38, q = i % 38;
        *(float4*)&As[r][q * 4] = *(const float4*)(g_A + (size_t)(s0 + r) * HP + q * 4);
    }
    for (int i = tid; i < 17 * 38; i += 256) {
        int r = i / 38, q = i % 38;
        int gr = s0 + r;
        float4 v = make_float4(0.f, 0.f, 0.f, 0.f);
        if (gr < Ldim) v = *(const float4*)(g_B + (size_t)gr * HP + q * 4);
        *(float4*)&Bs[r][q * 4] = v;
    }
    for (int i = tid; i < 17 * 38; i += 256) {
        int r = i / 38, q = i % 38;
        int gr = s0 + r;
        float4 v = make_float4(0.f, 0.f, 0.f, 0.f);
        if (gr < Ldim) v = *(const float4*)(g_C + (size_t)gr * HP + q * 4);
        *(float4*)&Cs[r][q * 4] = v;
    }
    __syncthreads();

    const int warp = tid >> 5, lane = tid & 31;
#pragma unroll
    for (int rowi = warp; rowi < 80; rowi += 8) {
        const int n     = (rowi >> 3) + 1;
        const int si    = rowi & 7;
        const int start = s0 + si;
        if (start >= Ldim - n + 1) continue;

        float wj[MAXN];
        float mx = -1e30f;
        for (int j = 0; j < n; j++) mx = fmaxf(mx, attw[si + j]);
        float ssum = 0.f;
        for (int j = 0; j < n; j++) {
            float e = __expf(attw[si + j] - mx);
            wj[j] = e; ssum += e;
        }
        float inv = 1.f / ssum;

        const int off = (n - 1) * (Ldim + 1) - (n * (n - 1)) / 2;
        float* outp = g_X + (size_t)(off + start) * HP;
#pragma unroll
        for (int k = 0; k < 5; k++) {
            int c = lane + 32 * k;
            if (c < Hdim) {
                float pool = 0.f;
                for (int j = 0; j < n; j++) pool += wj[j] * Cs[si + j][c];
                float v = As[si][c] + Bs[si + n - 1][c] + sb1s[c] + pool * inv;
                outp[c] = fmaxf(v, 0.f);
            }
        }
    }
}

// ---------------------------------------------------------------------------
extern "C" void kernel_launch(void* const* d_in, const int* in_sizes, int n_in,
                              void* d_out, int out_size)
{
    const float* embeds = (const float*)d_in[0];
    const float* states = (const float*)d_in[1];
    const float* aW1    = (const float*)d_in[2];
    const float* ab1    = (const float*)d_in[3];
    const float* aW2    = (const float*)d_in[4];
    const float* ab2    = (const float*)d_in[5];
    const float* aW3    = (const float*)d_in[6];
    const float* ab3    = (const float*)d_in[7];
    const float* sW1    = (const float*)d_in[8];
    const float* sb1    = (const float*)d_in[9];
    const float* sW2    = (const float*)d_in[10];
    const float* sb2    = (const float*)d_in[11];
    const float* sW3    = (const float*)d_in[12];
    const float* sb3    = (const float*)d_in[13];
    float* out = (float*)d_out;

    cudaFuncSetAttribute(mma_main<4, 1, 0>,
                         cudaFuncAttributeMaxDynamicSharedMemorySize, 67072);
    cudaFuncSetAttribute(mma_main<2, 2, 3>,
                         cudaFuncAttributeMaxDynamicSharedMemorySize, 51456);
    cudaFuncSetAttribute(mma_attn,
                         cudaFuncAttributeMaxDynamicSharedMemorySize, 43648);

    // weight splits (fp16 dup-slot + job2 triplets + vectors)
    split_w<<<622, 256>>>(sW1, aW1, aW2, sW2, sW3, sb2, aW3, ab2);
    // precompute GEMMs: g_A, g_B, H1-triplets, g_C  (fp16 2-slot)
    mma_main<4, 1, 0><<<dim3(32, 4), 320, 67072>>>(ab1, nullptr,
                                                   const_cast<float*>(embeds), states);
    // attn layer2+3 -> g_attn
    mma_attn<<<128, 320, 43648>>>(ab3);
    // pooled rows -> g_X
    pool_kernel<<<512, 256>>>(sb1);
    // final GEMM + fused layer3 -> out  (fp16 2-slot)
    mma_main<2, 2, 3><<<dim3(640, 1), 320, 51456>>>(nullptr, sb3, out, nullptr);
}